// round 10
// baseline (speedup 1.0000x reference)
#include <cuda_runtime.h>
#include <cuda_bf16.h>

// Wrapped SAT box query.
// Reference decomposes separably: result[n,c] = sum_{a in Rset} sum_{b in Cset}
//   sgn_a*sgn_b * sat[ia, ib, c], where each axis contributes 2 (no wrap) or 3
//   (wrap) terms. Terms with index < 0 contribute 0 (reference's "bad" mask).
//
// i(u) = floor(u*512 - 0.5). u*512 is exact (power of two), -0.5 exact at these
// magnitudes -> indices match the JAX reference bitwise. All coordinate math
// uses single round-to-nearest ops (__fmul_rn/__fadd_rn/__fsub_rn) to mirror
// the reference's unfused op sequence.

#define HDIM 512
#define WDIM 512

__device__ __forceinline__ int sat_index(float u) {
    // floor(u * 512 - 0.5), exact
    return (int)floorf(__fsub_rn(__fmul_rn(u, 512.0f), 0.5f));
}

__global__ void sat_query_kernel(
    const float* __restrict__ sat,
    const float* __restrict__ x,
    const int*   __restrict__ p_start,
    float*       __restrict__ out,
    int C, int C_out)
{
    const int n = blockIdx.x;

    // ---- scalar setup (redundant per thread; cheap) ----
    const float4 q = __ldg(reinterpret_cast<const float4*>(x) + n);
    float cu = q.x, cv = q.y, du = q.z, dv = q.w;

    float hu = __fmul_rn(du, 0.5f);
    float hv = __fmul_rn(dv, 0.5f);
    float su = __fsub_rn(cu, hu), eu = __fadd_rn(cu, hu);
    float sv = __fsub_rn(cv, hv), ev = __fadd_rn(cv, hv);

    // nsuv = where(d<0, euv, suv); neuv = where(d<0, suv, euv)
    if (du < 0.0f) { float t = su; su = eu; eu = t; }
    if (dv < 0.0f) { float t = sv; sv = ev; ev = t; }

    // frac wrap (single sub, matches reference)
    su = __fsub_rn(su, floorf(su)); eu = __fsub_rn(eu, floorf(eu));
    sv = __fsub_rn(sv, floorf(sv)); ev = __fsub_rn(ev, floorf(ev));

    // ---- per-axis inclusion-exclusion lists (3 slots, dead slot => sign 0) ----
    // Rows (u axis, H):
    int   iu_e = sat_index(eu);        // in [-1, 511]
    int   iu_s = sat_index(su) - 1;    // in [-2, 510]  == i(su - 1/H)
    bool  wu   = (su > eu);            // wrap case
    int   rI0 = (iu_e >= 0) ? iu_e : 0;  float rS0 = (iu_e >= 0) ? 1.0f : 0.0f;
    int   rI1 = wu ? (HDIM - 1) : 0;     float rS1 = wu ? 1.0f : 0.0f;
    int   rI2 = (iu_s >= 0) ? iu_s : 0;  float rS2 = (iu_s >= 0) ? -1.0f : 0.0f;

    // Cols (v axis, W):
    int   iv_e = sat_index(ev);
    int   iv_s = sat_index(sv) - 1;
    bool  wv   = (sv > ev);
    int   cI0 = (iv_e >= 0) ? iv_e : 0;  float cS0 = (iv_e >= 0) ? 1.0f : 0.0f;
    int   cI1 = wv ? (WDIM - 1) : 0;     float cS1 = wv ? 1.0f : 0.0f;
    int   cI2 = (iv_s >= 0) ? iv_s : 0;  float cS2 = (iv_s >= 0) ? -1.0f : 0.0f;

    const int WC = WDIM * C;
    int r0 = rI0 * WC, r1 = rI1 * WC, r2 = rI2 * WC;
    int c0 = cI0 * C,  c1 = cI1 * C,  c2 = cI2 * C;

    // 9 combined offsets / signs (all compile-time-named registers)
    const int o00 = r0 + c0, o01 = r0 + c1, o02 = r0 + c2;
    const int o10 = r1 + c0, o11 = r1 + c1, o12 = r1 + c2;
    const int o20 = r2 + c0, o21 = r2 + c1, o22 = r2 + c2;
    const float w00 = rS0 * cS0, w01 = rS0 * cS1, w02 = rS0 * cS2;
    const float w10 = rS1 * cS0, w11 = rS1 * cS1, w12 = rS1 * cS2;
    const float w20 = rS2 * cS0, w21 = rS2 * cS1, w22 = rS2 * cS2;

    // channel slice offset (start_idx >= 0 selects a channel window)
    int s0 = *p_start;
    if (s0 < 0) s0 = 0;
    const float* __restrict__ satc = sat + s0;

    const size_t obase = (size_t)n * (size_t)C_out;

    // ---- channel loop: 9 independent loads -> full MLP, coalesced across tid ----
    for (int ch = threadIdx.x; ch < C_out; ch += blockDim.x) {
        float acc;
        acc = __fmul_rn(w00, satc[o00 + ch]);
        acc = fmaf(w01, satc[o01 + ch], acc);
        acc = fmaf(w02, satc[o02 + ch], acc);
        acc = fmaf(w10, satc[o10 + ch], acc);
        acc = fmaf(w11, satc[o11 + ch], acc);
        acc = fmaf(w12, satc[o12 + ch], acc);
        acc = fmaf(w20, satc[o20 + ch], acc);
        acc = fmaf(w21, satc[o21 + ch], acc);
        acc = fmaf(w22, satc[o22 + ch], acc);
        out[obase + ch] = acc;
    }
}

extern "C" void kernel_launch(void* const* d_in, const int* in_sizes, int n_in,
                              void* d_out, int out_size) {
    const float* sat   = (const float*)d_in[0];
    const float* x     = (const float*)d_in[1];
    const int*   start = (const int*)d_in[2];
    // d_in[3] (len_idx) is implied by out_size

    const int N     = in_sizes[1] / 4;
    const int C     = in_sizes[0] / (HDIM * WDIM);
    const int C_out = out_size / N;

    int bd = C_out;
    if (bd > 1024) bd = 1024;
    bd = ((bd + 31) / 32) * 32;
    if (bd < 32) bd = 32;

    sat_query_kernel<<<N, bd>>>(sat, x, start, (float*)d_out, C, C_out);
}

// round 11
// speedup vs baseline: 1.0042x; 1.0042x over previous
#include <cuda_runtime.h>
#include <cuda_bf16.h>

// Wrapped SAT box query.
// Reference decomposes separably: result[n,c] = sum_{a in Rset} sum_{b in Cset}
//   sgn_a*sgn_b * sat[ia, ib, c], where each axis contributes 2 (no wrap) or 3
//   (wrap) terms. Terms with index < 0 contribute 0 (reference's "bad" mask).
//
// i(u) = floor(u*512 - 0.5). u*512 is exact (power of two), -0.5 exact at these
// magnitudes -> indices match the JAX reference bitwise. All coordinate math
// uses single round-to-nearest ops (__fmul_rn/__fadd_rn/__fsub_rn) to mirror
// the reference's unfused op sequence.

#define HDIM 512
#define WDIM 512

__device__ __forceinline__ int sat_index(float u) {
    // floor(u * 512 - 0.5), exact
    return (int)floorf(__fsub_rn(__fmul_rn(u, 512.0f), 0.5f));
}

__global__ void sat_query_kernel(
    const float* __restrict__ sat,
    const float* __restrict__ x,
    const int*   __restrict__ p_start,
    float*       __restrict__ out,
    int C, int C_out)
{
    const int n = blockIdx.x;

    // ---- scalar setup (redundant per thread; cheap) ----
    const float4 q = __ldg(reinterpret_cast<const float4*>(x) + n);
    float cu = q.x, cv = q.y, du = q.z, dv = q.w;

    float hu = __fmul_rn(du, 0.5f);
    float hv = __fmul_rn(dv, 0.5f);
    float su = __fsub_rn(cu, hu), eu = __fadd_rn(cu, hu);
    float sv = __fsub_rn(cv, hv), ev = __fadd_rn(cv, hv);

    // nsuv = where(d<0, euv, suv); neuv = where(d<0, suv, euv)
    if (du < 0.0f) { float t = su; su = eu; eu = t; }
    if (dv < 0.0f) { float t = sv; sv = ev; ev = t; }

    // frac wrap (single sub, matches reference)
    su = __fsub_rn(su, floorf(su)); eu = __fsub_rn(eu, floorf(eu));
    sv = __fsub_rn(sv, floorf(sv)); ev = __fsub_rn(ev, floorf(ev));

    // ---- per-axis inclusion-exclusion lists (3 slots, dead slot => sign 0) ----
    // Rows (u axis, H):
    int   iu_e = sat_index(eu);        // in [-1, 511]
    int   iu_s = sat_index(su) - 1;    // in [-2, 510]  == i(su - 1/H)
    bool  wu   = (su > eu);            // wrap case
    int   rI0 = (iu_e >= 0) ? iu_e : 0;  float rS0 = (iu_e >= 0) ? 1.0f : 0.0f;
    int   rI1 = wu ? (HDIM - 1) : 0;     float rS1 = wu ? 1.0f : 0.0f;
    int   rI2 = (iu_s >= 0) ? iu_s : 0;  float rS2 = (iu_s >= 0) ? -1.0f : 0.0f;

    // Cols (v axis, W):
    int   iv_e = sat_index(ev);
    int   iv_s = sat_index(sv) - 1;
    bool  wv   = (sv > ev);
    int   cI0 = (iv_e >= 0) ? iv_e : 0;  float cS0 = (iv_e >= 0) ? 1.0f : 0.0f;
    int   cI1 = wv ? (WDIM - 1) : 0;     float cS1 = wv ? 1.0f : 0.0f;
    int   cI2 = (iv_s >= 0) ? iv_s : 0;  float cS2 = (iv_s >= 0) ? -1.0f : 0.0f;

    const int WC = WDIM * C;
    int r0 = rI0 * WC, r1 = rI1 * WC, r2 = rI2 * WC;
    int c0 = cI0 * C,  c1 = cI1 * C,  c2 = cI2 * C;

    // 9 combined offsets / signs (all compile-time-named registers)
    const int o00 = r0 + c0, o01 = r0 + c1, o02 = r0 + c2;
    const int o10 = r1 + c0, o11 = r1 + c1, o12 = r1 + c2;
    const int o20 = r2 + c0, o21 = r2 + c1, o22 = r2 + c2;
    const float w00 = rS0 * cS0, w01 = rS0 * cS1, w02 = rS0 * cS2;
    const float w10 = rS1 * cS0, w11 = rS1 * cS1, w12 = rS1 * cS2;
    const float w20 = rS2 * cS0, w21 = rS2 * cS1, w22 = rS2 * cS2;

    // channel slice offset (start_idx >= 0 selects a channel window)
    int s0 = *p_start;
    if (s0 < 0) s0 = 0;
    const float* __restrict__ satc = sat + s0;

    const size_t obase = (size_t)n * (size_t)C_out;

    // ---- channel loop: 9 independent loads -> full MLP, coalesced across tid ----
    for (int ch = threadIdx.x; ch < C_out; ch += blockDim.x) {
        float acc;
        acc = __fmul_rn(w00, satc[o00 + ch]);
        acc = fmaf(w01, satc[o01 + ch], acc);
        acc = fmaf(w02, satc[o02 + ch], acc);
        acc = fmaf(w10, satc[o10 + ch], acc);
        acc = fmaf(w11, satc[o11 + ch], acc);
        acc = fmaf(w12, satc[o12 + ch], acc);
        acc = fmaf(w20, satc[o20 + ch], acc);
        acc = fmaf(w21, satc[o21 + ch], acc);
        acc = fmaf(w22, satc[o22 + ch], acc);
        out[obase + ch] = acc;
    }
}

extern "C" void kernel_launch(void* const* d_in, const int* in_sizes, int n_in,
                              void* d_out, int out_size) {
    const float* sat   = (const float*)d_in[0];
    const float* x     = (const float*)d_in[1];
    const int*   start = (const int*)d_in[2];
    // d_in[3] (len_idx) is implied by out_size

    const int N     = in_sizes[1] / 4;
    const int C     = in_sizes[0] / (HDIM * WDIM);
    const int C_out = out_size / N;

    int bd = C_out;
    if (bd > 1024) bd = 1024;
    bd = ((bd + 31) / 32) * 32;
    if (bd < 32) bd = 32;

    sat_query_kernel<<<N, bd>>>(sat, x, start, (float*)d_out, C, C_out);
}

// round 12
// speedup vs baseline: 2.5863x; 2.5755x over previous
#include <cuda_runtime.h>
#include <cuda_bf16.h>

// Wrapped SAT box query, separable inclusion-exclusion form:
//   result[n,c] = sum_{a in Rset} sum_{b in Cset} sgn_a*sgn_b * sat[ia, ib, c]
// Each axis contributes up to 3 (index, sign) terms; dead terms get sign 0 and
// index 0. Index math i(u)=floor(u*512-0.5) is exact and matches JAX bitwise.
//
// R11: float4 vectorization. Each thread handles 4 channels -> 9x LDG.128
// (144 B outstanding per thread, 4x the MLP of the scalar version), 1/4 the
// threads, 1/4 the redundant per-point setup. 4 points per block (72x4).

#define HDIM 512
#define WDIM 512

__device__ __forceinline__ int sat_index(float u) {
    // floor(u * 512 - 0.5), exact
    return (int)floorf(__fsub_rn(__fmul_rn(u, 512.0f), 0.5f));
}

__global__ void sat_query_v4_kernel(
    const float* __restrict__ sat,
    const float* __restrict__ x,
    const int*   __restrict__ p_start,
    float*       __restrict__ out,
    int C, int C_out, int N)
{
    const int n = blockIdx.x * blockDim.y + threadIdx.y;
    if (n >= N) return;

    // hoist the (uniform, L1-hot) start_idx load so it overlaps setup math
    int s0 = *p_start;
    if (s0 < 0) s0 = 0;

    // ---- per-point scalar setup (redundant across the 72 lanes; cheap) ----
    const float4 q = __ldg(reinterpret_cast<const float4*>(x) + n);
    float cu = q.x, cv = q.y, du = q.z, dv = q.w;

    float hu = __fmul_rn(du, 0.5f);
    float hv = __fmul_rn(dv, 0.5f);
    float su = __fsub_rn(cu, hu), eu = __fadd_rn(cu, hu);
    float sv = __fsub_rn(cv, hv), ev = __fadd_rn(cv, hv);

    if (du < 0.0f) { float t = su; su = eu; eu = t; }
    if (dv < 0.0f) { float t = sv; sv = ev; ev = t; }

    su = __fsub_rn(su, floorf(su)); eu = __fsub_rn(eu, floorf(eu));
    sv = __fsub_rn(sv, floorf(sv)); ev = __fsub_rn(ev, floorf(ev));

    // ---- per-axis inclusion-exclusion lists (3 slots, dead slot => sign 0) ----
    int   iu_e = sat_index(eu);
    int   iu_s = sat_index(su) - 1;
    bool  wu   = (su > eu);
    int   rI0 = (iu_e >= 0) ? iu_e : 0;  float rS0 = (iu_e >= 0) ? 1.0f : 0.0f;
    int   rI1 = wu ? (HDIM - 1) : 0;     float rS1 = wu ? 1.0f : 0.0f;
    int   rI2 = (iu_s >= 0) ? iu_s : 0;  float rS2 = (iu_s >= 0) ? -1.0f : 0.0f;

    int   iv_e = sat_index(ev);
    int   iv_s = sat_index(sv) - 1;
    bool  wv   = (sv > ev);
    int   cI0 = (iv_e >= 0) ? iv_e : 0;  float cS0 = (iv_e >= 0) ? 1.0f : 0.0f;
    int   cI1 = wv ? (WDIM - 1) : 0;     float cS1 = wv ? 1.0f : 0.0f;
    int   cI2 = (iv_s >= 0) ? iv_s : 0;  float cS2 = (iv_s >= 0) ? -1.0f : 0.0f;

    const int WC = WDIM * C;
    int r0 = rI0 * WC, r1 = rI1 * WC, r2 = rI2 * WC;
    int c0 = cI0 * C,  c1 = cI1 * C,  c2 = cI2 * C;

    const int o00 = r0 + c0, o01 = r0 + c1, o02 = r0 + c2;
    const int o10 = r1 + c0, o11 = r1 + c1, o12 = r1 + c2;
    const int o20 = r2 + c0, o21 = r2 + c1, o22 = r2 + c2;
    const float w00 = rS0 * cS0, w01 = rS0 * cS1, w02 = rS0 * cS2;
    const float w10 = rS1 * cS0, w11 = rS1 * cS1, w12 = rS1 * cS2;
    const float w20 = rS2 * cS0, w21 = rS2 * cS1, w22 = rS2 * cS2;

    const float* __restrict__ satc = sat + s0;
    const size_t obase = (size_t)n * (size_t)C_out;

    const int ch = threadIdx.x * 4;
    if (ch >= C_out) return;

    const bool aligned = ((C & 3) == 0) && ((s0 & 3) == 0) && (ch + 4 <= C_out);

    if (aligned) {
        // ---- fast path: 9 independent LDG.128, 3 independent FMA chains ----
        const float4* __restrict__ p = reinterpret_cast<const float4*>(satc + ch);
        // offsets are multiples of 4 floats -> divide for float4 indexing
        float4 v00 = __ldg(p + (o00 >> 2));
        float4 v01 = __ldg(p + (o01 >> 2));
        float4 v02 = __ldg(p + (o02 >> 2));
        float4 v10 = __ldg(p + (o10 >> 2));
        float4 v11 = __ldg(p + (o11 >> 2));
        float4 v12 = __ldg(p + (o12 >> 2));
        float4 v20 = __ldg(p + (o20 >> 2));
        float4 v21 = __ldg(p + (o21 >> 2));
        float4 v22 = __ldg(p + (o22 >> 2));

        float4 a, b, d;
        a.x = __fmul_rn(w00, v00.x); b.x = __fmul_rn(w01, v01.x); d.x = __fmul_rn(w02, v02.x);
        a.y = __fmul_rn(w00, v00.y); b.y = __fmul_rn(w01, v01.y); d.y = __fmul_rn(w02, v02.y);
        a.z = __fmul_rn(w00, v00.z); b.z = __fmul_rn(w01, v01.z); d.z = __fmul_rn(w02, v02.z);
        a.w = __fmul_rn(w00, v00.w); b.w = __fmul_rn(w01, v01.w); d.w = __fmul_rn(w02, v02.w);

        a.x = fmaf(w10, v10.x, a.x); b.x = fmaf(w11, v11.x, b.x); d.x = fmaf(w12, v12.x, d.x);
        a.y = fmaf(w10, v10.y, a.y); b.y = fmaf(w11, v11.y, b.y); d.y = fmaf(w12, v12.y, d.y);
        a.z = fmaf(w10, v10.z, a.z); b.z = fmaf(w11, v11.z, b.z); d.z = fmaf(w12, v12.z, d.z);
        a.w = fmaf(w10, v10.w, a.w); b.w = fmaf(w11, v11.w, b.w); d.w = fmaf(w12, v12.w, d.w);

        a.x = fmaf(w20, v20.x, a.x); b.x = fmaf(w21, v21.x, b.x); d.x = fmaf(w22, v22.x, d.x);
        a.y = fmaf(w20, v20.y, a.y); b.y = fmaf(w21, v21.y, b.y); d.y = fmaf(w22, v22.y, d.y);
        a.z = fmaf(w20, v20.z, a.z); b.z = fmaf(w21, v21.z, b.z); d.z = fmaf(w22, v22.z, d.z);
        a.w = fmaf(w20, v20.w, a.w); b.w = fmaf(w21, v21.w, b.w); d.w = fmaf(w22, v22.w, d.w);

        float4 r;
        r.x = __fadd_rn(__fadd_rn(a.x, b.x), d.x);
        r.y = __fadd_rn(__fadd_rn(a.y, b.y), d.y);
        r.z = __fadd_rn(__fadd_rn(a.z, b.z), d.z);
        r.w = __fadd_rn(__fadd_rn(a.w, b.w), d.w);

        *reinterpret_cast<float4*>(out + obase + ch) = r;
    } else {
        // ---- generic scalar path (sliced / tail channels) ----
        #pragma unroll
        for (int k = 0; k < 4; k++) {
            int c = ch + k;
            if (c >= C_out) break;
            float acc;
            acc = __fmul_rn(w00, satc[o00 + c]);
            acc = fmaf(w01, satc[o01 + c], acc);
            acc = fmaf(w02, satc[o02 + c], acc);
            acc = fmaf(w10, satc[o10 + c], acc);
            acc = fmaf(w11, satc[o11 + c], acc);
            acc = fmaf(w12, satc[o12 + c], acc);
            acc = fmaf(w20, satc[o20 + c], acc);
            acc = fmaf(w21, satc[o21 + c], acc);
            acc = fmaf(w22, satc[o22 + c], acc);
            out[obase + c] = acc;
        }
    }
}

extern "C" void kernel_launch(void* const* d_in, const int* in_sizes, int n_in,
                              void* d_out, int out_size) {
    const float* sat   = (const float*)d_in[0];
    const float* x     = (const float*)d_in[1];
    const int*   start = (const int*)d_in[2];

    const int N     = in_sizes[1] / 4;
    const int C     = in_sizes[0] / (HDIM * WDIM);
    const int C_out = out_size / N;

    int lanes = (C_out + 3) / 4;          // float4 lanes per point (72 for C=288)
    if (lanes < 1) lanes = 1;
    if (lanes > 1024) lanes = 1024;

    int ppb = 1024 / lanes;               // points per block
    if (ppb > 4) ppb = 4;
    if (ppb < 1) ppb = 1;

    dim3 bd(lanes, ppb);
    int grid = (N + ppb - 1) / ppb;

    sat_query_v4_kernel<<<grid, bd>>>(sat, x, start, (float*)d_out, C, C_out, N);
}